// round 5
// baseline (speedup 1.0000x reference)
#include <cuda_runtime.h>

// PositionalEncoding: out[b,s,d] = x[b,s,d] + pe[s,d]
//   pe[s,d] = sin(s / 10000^((d/2)/4096)) if d even else cos(...)
// Shapes fixed: B=8, S=4096, D=1024, fp32.
//
// R4: same proven structure (one thread per float4 of the (S,D) pe plane,
// pe computed once and reused across all 8 batch planes), but planes
// processed in two groups of 4 to cut register pressure (48 -> ~36 regs)
// while keeping 4 LDG.128 in flight per group. Tests whether high
// occupancy + front-batched loads moves the DRAM ceiling; expected
// neutral (kernel pinned at HBM 1:1 R/W mix cap ~75%).

namespace {
constexpr int B = 8;
constexpr int GROUP = 4;               // planes per load batch
constexpr int S = 4096;
constexpr int D = 1024;
constexpr int PLANE4 = S * D / 4;      // 1,048,576 float4 per batch plane
constexpr int D4 = D / 4;              // 256 float4 per row
constexpr int THREADS = 256;
// log2(10000) / 4096
__device__ __forceinline__ float k_scale() { return 13.287712379549449f / 4096.0f; }
}

__global__ __launch_bounds__(THREADS) void pe_add_kernel(const float4* __restrict__ x,
                                                         float4* __restrict__ out) {
    const int idx = blockIdx.x * blockDim.x + threadIdx.x;   // exact grid: [0, PLANE4)

    const int pos = idx >> 8;          // sequence position (row)
    const int c4  = idx & (D4 - 1);    // float4 column within row
    const float k0 = (float)(2 * c4);  // k for d0,d1 ; k0+1 for d2,d3
    const float fpos = (float)pos;

    // pe computed once (hidden under the first load group):
    // 10000^(k/4096) = exp2(k * log2(10000)/4096)
    const float a0 = fpos / exp2f(k0 * k_scale());
    const float a1 = fpos / exp2f((k0 + 1.0f) * k_scale());
    float s0, c0, s1, c1;
    sincosf(a0, &s0, &c0);
    sincosf(a1, &s1, &c1);

#pragma unroll
    for (int g = 0; g < B / GROUP; ++g) {
        float4 v[GROUP];
#pragma unroll
        for (int j = 0; j < GROUP; ++j) {
            v[j] = x[(size_t)(g * GROUP + j) * PLANE4 + (size_t)idx];
        }
#pragma unroll
        for (int j = 0; j < GROUP; ++j) {
            v[j].x += s0;   // d even -> sin
            v[j].y += c0;   // d odd  -> cos
            v[j].z += s1;
            v[j].w += c1;
            out[(size_t)(g * GROUP + j) * PLANE4 + (size_t)idx] = v[j];
        }
    }
}

extern "C" void kernel_launch(void* const* d_in, const int* in_sizes, int n_in,
                              void* d_out, int out_size) {
    (void)in_sizes; (void)n_in; (void)out_size;
    const float4* x = (const float4*)d_in[0];
    float4* out = (float4*)d_out;
    pe_add_kernel<<<PLANE4 / THREADS, THREADS>>>(x, out);   // 4096 blocks
}

// round 6
// speedup vs baseline: 1.0471x; 1.0471x over previous
#include <cuda_runtime.h>

// PositionalEncoding: out[b,s,d] = x[b,s,d] + pe[s,d]
//   pe[s,d] = sin(s / 10000^((d/2)/4096)) if d even else cos(...)
// Shapes fixed: B=8, S=4096, D=1024, fp32.
//
// FINAL (== R3, best measured: 36.19us kernel / 43.5us bench).
// Converged at the HBM roofline: 256 MiB minimal traffic at 5.9 TB/s
// (~75% of spec = 1:1 R/W-mix turnaround ceiling). Verified slack in
// occupancy (49% vs 83% identical perf), MLP shape (4 vs 8 identical),
// and cache policy (.cs regressed). pe is computed once per (s,d) float4
// and reused across all 8 batch planes, so transcendental cost is /8 and
// fully hidden behind the DRAM stream.

namespace {
constexpr int B = 8;
constexpr int S = 4096;
constexpr int D = 1024;
constexpr int PLANE4 = S * D / 4;      // 1,048,576 float4 per batch plane
constexpr int D4 = D / 4;              // 256 float4 per row
constexpr int THREADS = 256;
// log2(10000) / 4096
__device__ __forceinline__ float k_scale() { return 13.287712379549449f / 4096.0f; }
}

__global__ __launch_bounds__(THREADS) void pe_add_kernel(const float4* __restrict__ x,
                                                         float4* __restrict__ out) {
    const int idx = blockIdx.x * blockDim.x + threadIdx.x;   // exact grid: [0, PLANE4)

    const int pos = idx >> 8;          // sequence position (row)
    const int c4  = idx & (D4 - 1);    // float4 column within row
    // d = 4*c4..4*c4+3 ; k = d>>1 -> k0 = 2*c4 (d0,d1), k1 = k0+1 (d2,d3)
    const float k0 = (float)(2 * c4);
    const float fpos = (float)pos;

    // Issue all 8 plane loads first — maximize outstanding LDG.128.
    float4 v[B];
#pragma unroll
    for (int b = 0; b < B; ++b) {
        v[b] = x[(size_t)b * PLANE4 + (size_t)idx];
    }

    // pe (computed once, hidden under the loads): 10000^(k/4096) = exp2(k*c)
    const float a0 = fpos / exp2f(k0 * k_scale());
    const float a1 = fpos / exp2f((k0 + 1.0f) * k_scale());
    float s0, c0, s1, c1;
    sincosf(a0, &s0, &c0);
    sincosf(a1, &s1, &c1);

#pragma unroll
    for (int b = 0; b < B; ++b) {
        v[b].x += s0;   // d even -> sin
        v[b].y += c0;   // d odd  -> cos
        v[b].z += s1;
        v[b].w += c1;
        out[(size_t)b * PLANE4 + (size_t)idx] = v[b];
    }
}

extern "C" void kernel_launch(void* const* d_in, const int* in_sizes, int n_in,
                              void* d_out, int out_size) {
    (void)in_sizes; (void)n_in; (void)out_size;
    const float4* x = (const float4*)d_in[0];
    float4* out = (float4*)d_out;
    pe_add_kernel<<<PLANE4 / THREADS, THREADS>>>(x, out);   // 4096 blocks
}